// round 16
// baseline (speedup 1.0000x reference)
#include <cuda_runtime.h>
#include <cuda_bf16.h>
#include <cuda_fp16.h>
#include <math.h>
#include <stdint.h>

#define Bv   4
#define Nv   256
#define CIN  256
#define CH   128
#define Wv   256
#define Hv   256
#define HW   (Wv*Hv)
#define Sv   256

// ---------------- scratch ---------------------------------------------------
__device__ float g_nf[Bv*Nv*CH];                 // score-premultiplied normalized nf
__device__ float g_pw[Bv*Nv*4];                  // (K_sat R_sat^T) @ worldR, padded
__device__ __half g_sfnh[(size_t)Bv*HW*CH];      // normalized sat features, fp16
__device__ float g_cand[Bv*Sv*Nv*2];
__device__ float g_logits[Bv*Sv];
// A fragments in mma.m16n8k16 per-lane layout: [mb(8)][ks(16)][lane(32)]
__device__ uint4 g_WfH[8*16*32];                 // 16*W fp16

// ---------------- helpers ---------------------------------------------------
__device__ __forceinline__ uint32_t s2u(const void* p){
    uint32_t a;
    asm("{ .reg .u64 t; cvta.to.shared.u64 t, %1; cvt.u32.u64 %0, t; }" : "=r"(a) : "l"(p));
    return a;
}
__device__ __forceinline__ uint32_t packh2(float lo_e, float hi_e){
    uint32_t r;   // lower 16 bits <- lo_e (first in memory)
    asm("cvt.rn.f16x2.f32 %0, %1, %2;" : "=r"(r) : "f"(hi_e), "f"(lo_e));
    return r;
}
__device__ __forceinline__ void ldsm4t(uint32_t* r, uint32_t addr){
    asm volatile("ldmatrix.sync.aligned.m8n8.x4.trans.shared.b16 {%0,%1,%2,%3}, [%4];"
        : "=r"(r[0]), "=r"(r[1]), "=r"(r[2]), "=r"(r[3]) : "r"(addr));
}
__device__ __forceinline__ void mma16816(float* d, const uint32_t* a, const uint32_t* b){
    asm volatile("mma.sync.aligned.m16n8k16.row.col.f32.f16.f16.f32 "
        "{%0,%1,%2,%3}, {%4,%5,%6,%7}, {%8,%9}, {%0,%1,%2,%3};"
        : "+f"(d[0]), "+f"(d[1]), "+f"(d[2]), "+f"(d[3])
        : "r"(a[0]), "r"(a[1]), "r"(a[2]), "r"(a[3]), "r"(b[0]), "r"(b[1]));
}
__device__ __forceinline__ void cpa16(uint32_t dst, const void* src){
    asm volatile("cp.async.ca.shared.global [%0], [%1], 16;" :: "r"(dst), "l"(src));
}
__device__ __forceinline__ void cpa_commit(){ asm volatile("cp.async.commit_group;"); }
__device__ __forceinline__ void cpa_wait0(){ asm volatile("cp.async.wait_group 0;" ::: "memory"); }

// ---------------- K0: 16*W_sat -> fragment-layout fp16 (once) --------------
__global__ void k_wcvt(const float* __restrict__ Wsat) {
    int tid = blockIdx.x * 256 + threadIdx.x;   // 0..4095
    int lane = tid & 31, ks = (tid >> 5) & 15, mb = tid >> 9;
    int r = lane >> 2, c0 = (lane & 3) * 2;
    int row0 = mb * 16 + r, row1 = row0 + 8;
    int col0 = ks * 16 + c0, col2 = col0 + 8;
    float e[8];
    e[0] = Wsat[row0*CIN + col0]     * 16.f;
    e[1] = Wsat[row0*CIN + col0 + 1] * 16.f;
    e[2] = Wsat[row1*CIN + col0]     * 16.f;
    e[3] = Wsat[row1*CIN + col0 + 1] * 16.f;
    e[4] = Wsat[row0*CIN + col2]     * 16.f;
    e[5] = Wsat[row0*CIN + col2 + 1] * 16.f;
    e[6] = Wsat[row1*CIN + col2]     * 16.f;
    e[7] = Wsat[row1*CIN + col2 + 1] * 16.f;
    g_WfH[tid] = make_uint4(packh2(e[0],e[1]), packh2(e[2],e[3]),
                            packh2(e[4],e[5]), packh2(e[6],e[7]));
}

// ---------------- K1: nf = score * normalize(node_features @ Wn + bn) ------
__global__ void k_nf(const float* __restrict__ nfeat,
                     const float* __restrict__ Wn,
                     const float* __restrict__ bn,
                     const float* __restrict__ scores) {
    __shared__ float sf[8][CIN];
    __shared__ float red[8][128];
    __shared__ float sinv[8];
    int t = threadIdx.x;
    int cid = blockIdx.x;
    int b = cid >> 5;
    int n0 = (cid & 31) * 8;
    const float* src = nfeat + ((size_t)(b * Nv + n0)) * CIN;
    #pragma unroll
    for (int r = 0; r < 16; r++) {
        int idx = r * 128 + t;
        sf[idx >> 8][idx & 255] = src[idx];
    }
    __syncthreads();
    float acc[8];
    float bj = bn[t];
    #pragma unroll
    for (int i = 0; i < 8; i++) acc[i] = bj;
    for (int k = 0; k < CIN; k++) {
        float w = Wn[k * CH + t];
        #pragma unroll
        for (int i = 0; i < 8; i++) acc[i] += sf[i][k] * w;
    }
    #pragma unroll
    for (int i = 0; i < 8; i++) red[i][t] = acc[i] * acc[i];
    __syncthreads();
    if (t < 8) {
        float s = 0.f;
        for (int j = 0; j < 128; j++) s += red[t][j];
        sinv[t] = scores[b * Nv + n0 + t] / fmaxf(sqrtf(s), 1e-12f);
    }
    __syncthreads();
    #pragma unroll
    for (int i = 0; i < 8; i++)
        g_nf[(size_t)(b * Nv + n0 + i) * CH + t] = acc[i] * sinv[i];
}

// ---------------- K2: per-node projected ray endpoints ---------------------
__global__ void k_pw(const float* __restrict__ coords,
                     const float* __restrict__ depths,
                     const float* __restrict__ Kl,
                     const float* __restrict__ Rl,
                     const float* __restrict__ Ks,
                     const float* __restrict__ Rs) {
    int idx = blockIdx.x * blockDim.x + threadIdx.x;
    if (idx >= Bv * Nv) return;
    int b = idx / Nv;
    const float* K = Kl + b * 9;
    float a00=K[0],a01=K[1],a02=K[2],a10=K[3],a11=K[4],a12=K[5],a20=K[6],a21=K[7],a22=K[8];
    float c00 = a11*a22 - a12*a21, c01 = a02*a21 - a01*a22, c02 = a01*a12 - a02*a11;
    float c10 = a12*a20 - a10*a22, c11 = a00*a22 - a02*a20, c12 = a02*a10 - a00*a12;
    float c20 = a10*a21 - a11*a20, c21 = a01*a20 - a00*a21, c22 = a00*a11 - a01*a10;
    float det = a00*c00 + a01*c10 + a02*c20;
    float id = 1.0f / det;
    float u = coords[idx*2+0], v = coords[idx*2+1];
    float d = depths[idx];
    float cx = (c00*u + c01*v + c02) * id * d;
    float cy = (c10*u + c11*v + c12) * id * d;
    float cz = (c20*u + c21*v + c22) * id * d;
    const float* R = Rl + b * 9;
    float wx = R[0]*cx + R[1]*cy + R[2]*cz;
    float wy = R[3]*cx + R[4]*cy + R[5]*cz;
    float wz = R[6]*cx + R[7]*cy + R[8]*cz;
    const float* Km = Ks + b * 9;
    const float* Rm = Rs + b * 9;
    float P[9];
    #pragma unroll
    for (int i = 0; i < 3; i++)
        #pragma unroll
        for (int j = 0; j < 3; j++)
            P[i*3+j] = Km[i*3+0]*Rm[j*3+0] + Km[i*3+1]*Rm[j*3+1] + Km[i*3+2]*Rm[j*3+2];
    g_pw[idx*4+0] = P[0]*wx + P[1]*wy + P[2]*wz;
    g_pw[idx*4+1] = P[3]*wx + P[4]*wy + P[5]*wz;
    g_pw[idx*4+2] = P[6]*wx + P[7]*wy + P[8]*wz;
    g_pw[idx*4+3] = 0.f;
}

// ---------------- K3: sf_norm, single-fp16 A via LDG, B via cp.async -------
#define B_PITCH 272
#define BBUF    8704
#define OFF_B   0
#define OFF_S   17408
#define SMEM_K3 67584    // epilogue stage (128 x 132 fp32) dominates

__global__ __launch_bounds__(256, 2) void k_sfmma(const float* __restrict__ feat,
                                                  const float* __restrict__ bsat) {
    extern __shared__ char dsm[];
    __shared__ float s_inv[128];
    uint32_t sb = s2u(dsm);

    int t = threadIdx.x, wid = t >> 5, lane = t & 31;
    int warp_m = wid & 3, warp_n = wid >> 2;
    int b = blockIdx.y, p0 = blockIdx.x * 128;
    const float* fb = feat + (size_t)b * CIN * HW + p0;

    auto issueB = [&](int chunk){
        #pragma unroll
        for (int j = 0; j < 4; j++) {
            int idx = j * 256 + t;
            int c = idx >> 5, pxg = idx & 31;
            cpa16(sb + OFF_S + idx * 16, fb + (size_t)(chunk * 32 + c) * HW + pxg * 4);
        }
        cpa_commit();
    };
    auto convB = [&](int buf){
        #pragma unroll
        for (int j = 0; j < 4; j++) {
            int idx = j * 256 + t;
            int c = idx >> 5, pxg = idx & 31;
            float4 v = *(const float4*)(dsm + OFF_S + idx * 16);
            uint2 u = make_uint2(packh2(v.x, v.y), packh2(v.z, v.w));
            *(uint2*)(dsm + OFF_B + buf * BBUF + c * B_PITCH + pxg * 8) = u;
        }
    };

    issueB(0);
    cpa_wait0();
    convB(0);
    __syncthreads();

    uint32_t lrow = lane & 15;
    uint32_t bCol = (uint32_t)(warp_n * 64 + ((lane >> 4) & 1) * 8) * 2;
    int mb0 = warp_m * 2, mb1 = mb0 + 1;

    float acc[2][8][4];
    #pragma unroll
    for (int i = 0; i < 2; i++)
        #pragma unroll
        for (int j = 0; j < 8; j++)
            #pragma unroll
            for (int r = 0; r < 4; r++) acc[i][j][r] = 0.f;

    // A-fragment registers (current set for ksg=0)
    uint4 AH0 = __ldg(&g_WfH[(mb0 * 16 + 0) * 32 + lane]);
    uint4 AH1 = __ldg(&g_WfH[(mb1 * 16 + 0) * 32 + lane]);

    for (int c = 0; c < 8; c++) {
        if (c < 7) issueB(c + 1);
        uint32_t bbase = sb + OFF_B + (uint32_t)(c & 1) * BBUF;
        #pragma unroll
        for (int ks = 0; ks < 2; ks++) {
            int ksg = c * 2 + ks;
            int pk = (ksg < 15) ? (ksg + 1) : 15;
            // prefetch next A fragments (needed only next iteration)
            uint4 nAH0 = __ldg(&g_WfH[(mb0 * 16 + pk) * 32 + lane]);
            uint4 nAH1 = __ldg(&g_WfH[(mb1 * 16 + pk) * 32 + lane]);
            uint32_t bb[4][4];
            #pragma unroll
            for (int nf2 = 0; nf2 < 4; nf2++)
                ldsm4t(bb[nf2], bbase + (uint32_t)(ks * 16 + lrow) * B_PITCH
                                      + bCol + (uint32_t)nf2 * 32);
            const uint32_t* ah[2] = {(const uint32_t*)&AH0, (const uint32_t*)&AH1};
            #pragma unroll
            for (int nf2 = 0; nf2 < 4; nf2++)
                #pragma unroll
                for (int fm = 0; fm < 2; fm++) {
                    mma16816(acc[fm][2*nf2],     ah[fm], bb[nf2] + 0);
                    mma16816(acc[fm][2*nf2 + 1], ah[fm], bb[nf2] + 2);
                }
            AH0 = nAH0; AH1 = nAH1;
        }
        if (c < 7) { cpa_wait0(); convB((c + 1) & 1); }
        __syncthreads();
    }

    // ---- epilogue: stage [px][o] (scale+bias), per-px L2 norm, fp16 store --
    float* stg = (float*)dsm;          // 128 px x 132 floats
    const float SC = 0.0625f;
    float bias0[2], bias1[2];
    #pragma unroll
    for (int fm = 0; fm < 2; fm++) {
        int m = warp_m * 32 + fm * 16 + (lane >> 2);
        bias0[fm] = bsat[m];
        bias1[fm] = bsat[m + 8];
    }
    #pragma unroll
    for (int fm = 0; fm < 2; fm++) {
        int m0 = warp_m * 32 + fm * 16 + (lane >> 2);
        #pragma unroll
        for (int fn = 0; fn < 8; fn++) {
            int n0 = warp_n * 64 + fn * 8 + (lane & 3) * 2;
            stg[n0 * 132 + m0]           = acc[fm][fn][0] * SC + bias0[fm];
            stg[(n0 + 1) * 132 + m0]     = acc[fm][fn][1] * SC + bias0[fm];
            stg[n0 * 132 + m0 + 8]       = acc[fm][fn][2] * SC + bias1[fm];
            stg[(n0 + 1) * 132 + m0 + 8] = acc[fm][fn][3] * SC + bias1[fm];
        }
    }
    __syncthreads();
    if (t < 128) {
        float ss = 0.f;
        #pragma unroll
        for (int o4 = 0; o4 < 32; o4++) {
            float4 v = *(const float4*)&stg[t * 132 + o4 * 4];
            ss += v.x*v.x + v.y*v.y + v.z*v.z + v.w*v.w;
        }
        s_inv[t] = 1.0f / fmaxf(sqrtf(ss), 1e-12f);
    }
    __syncthreads();
    __half* outp = g_sfnh + ((size_t)b * HW + p0) * CH;
    #pragma unroll
    for (int it = 0; it < 8; it++) {
        int idx = it * 256 + t;
        int px = idx >> 4, cg = (idx & 15) * 8;
        float inv = s_inv[px];
        float4 v0 = *(const float4*)&stg[px * 132 + cg];
        float4 v1 = *(const float4*)&stg[px * 132 + cg + 4];
        uint4 o;
        o.x = packh2(v0.x * inv, v0.y * inv);
        o.y = packh2(v0.z * inv, v0.w * inv);
        o.z = packh2(v1.x * inv, v1.y * inv);
        o.w = packh2(v1.z * inv, v1.w * inv);
        *(uint4*)(outp + (size_t)px * CH + cg) = o;
    }
}

// ---------------- K4: 4 search positions per block -------------------------
__global__ __launch_bounds__(256) void k_sample(const float* __restrict__ Ksat,
                                                const float* __restrict__ Rsat,
                                                const float* __restrict__ tsat,
                                                const float* __restrict__ tinit,
                                                const float* __restrict__ radius) {
    int b = blockIdx.y;
    int s0 = blockIdx.x * 4;           // 4 positions, same row (4 | 16)
    int t = threadIdx.x;
    int w = t >> 5, lane = t & 31;
    __shared__ float warpsum[4][8];
    float rxs[4], rys[4], rzs[4];
    {
        const float* Km = Ksat + b * 9;
        const float* Rm = Rsat + b * 9;
        float rad = radius[b];
        float stepx = -1.f + (float)(s0 & 15) * (2.f / 15.f);
        float stepy = -1.f + (float)(s0 >> 4) * (2.f / 15.f);
        float dx = tinit[b*3+0] + stepx * rad - tsat[b*3+0];
        float dy = tinit[b*3+1] + stepy * rad - tsat[b*3+1];
        float dz = tinit[b*3+2] - tsat[b*3+2];
        float P[9];
        #pragma unroll
        for (int i = 0; i < 3; i++)
            #pragma unroll
            for (int j = 0; j < 3; j++)
                P[i*3+j] = Km[i*3+0]*Rm[j*3+0] + Km[i*3+1]*Rm[j*3+1] + Km[i*3+2]*Rm[j*3+2];
        float r0x = P[0]*dx + P[1]*dy + P[2]*dz;
        float r0y = P[3]*dx + P[4]*dy + P[5]*dz;
        float r0z = P[6]*dx + P[7]*dy + P[8]*dz;
        float ddx = (2.f / 15.f) * rad;
        #pragma unroll
        for (int sc = 0; sc < 4; sc++) {
            rxs[sc] = r0x + P[0] * ddx * (float)sc;
            rys[sc] = r0y + P[3] * ddx * (float)sc;
            rzs[sc] = r0z + P[6] * ddx * (float)sc;
        }
    }

    const float PXS = 256.0f / 255.0f;
    const __half* sfb = g_sfnh + (size_t)b * HW * CH;
    float lacc[4] = {0.f, 0.f, 0.f, 0.f};
    #pragma unroll 1
    for (int n = w; n < Nv; n += 8) {
        float4 pw  = *(const float4*)(g_pw + (b * Nv + n) * 4);
        float4 nfv = *(const float4*)(g_nf + (size_t)(b * Nv + n) * CH + lane * 4);
        #pragma unroll
        for (int sc = 0; sc < 4; sc++) {
            float ww = pw.z + rzs[sc];
            float cx = (pw.x + rxs[sc]) / ww;
            float cy = (pw.y + rys[sc]) / ww;
            if (lane == 0) {
                float2* cd = (float2*)(g_cand + ((size_t)(b*Sv + s0 + sc) * Nv) * 2);
                cd[n] = make_float2(cx, cy);
            }
            float px = cx * PXS - 0.5f, py = cy * PXS - 0.5f;
            float x0 = floorf(px), y0 = floorf(py);
            float fx = px - x0, fy = py - y0;
            float cw[4] = {(1.f-fy)*(1.f-fx), (1.f-fy)*fx, fy*(1.f-fx), fy*fx};
            float acc = 0.f;
            #pragma unroll
            for (int cc = 0; cc < 4; cc++) {
                float xf = x0 + (float)(cc & 1), yf = y0 + (float)(cc >> 1);
                float m = (xf >= 0.f && xf <= 255.f && yf >= 0.f && yf <= 255.f) ? 1.f : 0.f;
                int xi = min(max((int)xf, 0), 255), yi = min(max((int)yf, 0), 255);
                uint2 rr = *(const uint2*)(sfb + ((size_t)(yi * Wv + xi)) * CH + lane * 4);
                float2 h0 = __half22float2(*(__half2*)&rr.x);
                float2 h1 = __half22float2(*(__half2*)&rr.y);
                float d = nfv.x*h0.x + nfv.y*h0.y + nfv.z*h1.x + nfv.w*h1.y;
                acc += cw[cc] * m * d;
            }
            lacc[sc] += acc;
        }
    }
    #pragma unroll
    for (int sc = 0; sc < 4; sc++) {
        float v = lacc[sc];
        #pragma unroll
        for (int o = 16; o > 0; o >>= 1) v += __shfl_down_sync(0xffffffffu, v, o);
        if (lane == 0) warpsum[sc][w] = v;
    }
    __syncthreads();
    if (t < 4) {
        float s8 = 0.f;
        #pragma unroll
        for (int i = 0; i < 8; i++) s8 += warpsum[t][i];
        g_logits[b * Sv + s0 + t] = s8;
    }
}

// ---------------- K5: softmax, argmax, outputs -----------------------------
__global__ void k_final(float* __restrict__ out,
                        const float* __restrict__ tinit,
                        const float* __restrict__ radius,
                        const float* __restrict__ lscale) {
    int b = blockIdx.x;
    int t = threadIdx.x;   // 256
    __shared__ float sred[256];
    __shared__ int bestI;
    float escale = expf(lscale[0]);
    float L = g_logits[b * Sv + t] * escale;
    sred[t] = L; __syncthreads();
    for (int o = 128; o > 0; o >>= 1) {
        if (t < o) sred[t] = fmaxf(sred[t], sred[t + o]);
        __syncthreads();
    }
    float m = sred[0];
    __syncthreads();
    float e = expf(L - m);
    sred[t] = e; __syncthreads();
    for (int o = 128; o > 0; o >>= 1) {
        if (t < o) sred[t] += sred[t + o];
        __syncthreads();
    }
    float Z = sred[0];
    out[6144 + b * Sv + t] = e / Z;
    if (t == 0) bestI = 1 << 30;
    __syncthreads();
    if (L == m) atomicMin(&bestI, t);
    __syncthreads();
    int bi = bestI;
    float mx = g_cand[((size_t)(b * Sv + bi) * Nv + t) * 2 + 0];
    float my = g_cand[((size_t)(b * Sv + bi) * Nv + t) * 2 + 1];
    out[(b * Nv + t) * 2 + 0] = mx;
    out[(b * Nv + t) * 2 + 1] = my;
    out[2048 + b * Nv + t] =
        (mx >= 0.f && mx < (float)Wv && my >= 0.f && my < (float)Hv) ? 1.f : 0.f;
    float rad = radius[b];
    float sx = -1.f + (float)(t & 15) * (2.f / 15.f);
    float sy = -1.f + (float)(t >> 4) * (2.f / 15.f);
    out[3072 + (b * Sv + t) * 3 + 0] = tinit[b*3+0] + sx * rad;
    out[3072 + (b * Sv + t) * 3 + 1] = tinit[b*3+1] + sy * rad;
    out[3072 + (b * Sv + t) * 3 + 2] = tinit[b*3+2];
}

// ---------------- launch ----------------------------------------------------
extern "C" void kernel_launch(void* const* d_in, const int* in_sizes, int n_in,
                              void* d_out, int out_size) {
    const float* node_coords   = (const float*)d_in[0];
    const float* node_scores   = (const float*)d_in[1];
    const float* node_features = (const float*)d_in[2];
    const float* node_depths   = (const float*)d_in[3];
    const float* K_left        = (const float*)d_in[4];
    const float* R_left        = (const float*)d_in[5];
    const float* t_init        = (const float*)d_in[6];
    const float* sat_featmap   = (const float*)d_in[7];
    const float* K_sat         = (const float*)d_in[8];
    const float* R_sat         = (const float*)d_in[9];
    const float* t_sat         = (const float*)d_in[10];
    const float* radius        = (const float*)d_in[11];
    int off = (n_in >= 18) ? 0 : -1;
    const float* W_node      = (const float*)d_in[13 + off];
    const float* b_node      = (const float*)d_in[14 + off];
    const float* W_sat       = (const float*)d_in[15 + off];
    const float* b_sat       = (const float*)d_in[16 + off];
    const float* logit_scale = (const float*)d_in[17 + off];
    float* out = (float*)d_out;

    cudaFuncSetAttribute(k_sfmma, cudaFuncAttributeMaxDynamicSharedMemorySize, SMEM_K3);

    k_wcvt<<<16, 256>>>(W_sat);
    k_nf<<<128, 128>>>(node_features, W_node, b_node, node_scores);
    k_pw<<<4, 256>>>(node_coords, node_depths, K_left, R_left, K_sat, R_sat);
    k_sfmma<<<dim3(512, Bv), 256, SMEM_K3>>>(sat_featmap, b_sat);
    k_sample<<<dim3(Sv/4, Bv), 256>>>(K_sat, R_sat, t_sat, t_init, radius);
    k_final<<<Bv, 256>>>(out, t_init, radius, logit_scale);
}

// round 17
// speedup vs baseline: 1.1579x; 1.1579x over previous
#include <cuda_runtime.h>
#include <cuda_bf16.h>
#include <cuda_fp16.h>
#include <math.h>
#include <stdint.h>

#define Bv   4
#define Nv   256
#define CIN  256
#define CH   128
#define Wv   256
#define Hv   256
#define HW   (Wv*Hv)
#define Sv   256

// ---------------- scratch ---------------------------------------------------
__device__ float g_nf[Bv*Nv*CH];                 // score-premultiplied normalized nf
__device__ float g_pw[Bv*Nv*4];                  // (K_sat R_sat^T) @ worldR, padded
__device__ __half g_sfnh[(size_t)Bv*HW*CH];      // normalized sat features, fp16
__device__ float g_cand[Bv*Sv*Nv*2];
__device__ float g_logits[Bv*Sv];
// A fragments in mma.m16n8k16 per-lane layout: [mb(8)][ks(16)][lane(32)]
__device__ uint4 g_WfH[8*16*32];                 // 16*W fp16

// ---------------- helpers ---------------------------------------------------
__device__ __forceinline__ uint32_t s2u(const void* p){
    uint32_t a;
    asm("{ .reg .u64 t; cvta.to.shared.u64 t, %1; cvt.u32.u64 %0, t; }" : "=r"(a) : "l"(p));
    return a;
}
__device__ __forceinline__ uint32_t packh2(float lo_e, float hi_e){
    uint32_t r;   // lower 16 bits <- lo_e (first in memory)
    asm("cvt.rn.f16x2.f32 %0, %1, %2;" : "=r"(r) : "f"(hi_e), "f"(lo_e));
    return r;
}
__device__ __forceinline__ void ldsm4t(uint32_t* r, uint32_t addr){
    asm volatile("ldmatrix.sync.aligned.m8n8.x4.trans.shared.b16 {%0,%1,%2,%3}, [%4];"
        : "=r"(r[0]), "=r"(r[1]), "=r"(r[2]), "=r"(r[3]) : "r"(addr));
}
__device__ __forceinline__ void mma16816(float* d, const uint32_t* a, const uint32_t* b){
    asm volatile("mma.sync.aligned.m16n8k16.row.col.f32.f16.f16.f32 "
        "{%0,%1,%2,%3}, {%4,%5,%6,%7}, {%8,%9}, {%0,%1,%2,%3};"
        : "+f"(d[0]), "+f"(d[1]), "+f"(d[2]), "+f"(d[3])
        : "r"(a[0]), "r"(a[1]), "r"(a[2]), "r"(a[3]), "r"(b[0]), "r"(b[1]));
}
__device__ __forceinline__ void cpa16(uint32_t dst, const void* src){
    asm volatile("cp.async.ca.shared.global [%0], [%1], 16;" :: "r"(dst), "l"(src));
}
__device__ __forceinline__ void cpa_commit(){ asm volatile("cp.async.commit_group;"); }
__device__ __forceinline__ void cpa_wait0(){ asm volatile("cp.async.wait_group 0;" ::: "memory"); }

// ---------------- K0: 16*W_sat -> fragment-layout fp16 (once) --------------
__global__ void k_wcvt(const float* __restrict__ Wsat) {
    int tid = blockIdx.x * 256 + threadIdx.x;   // 0..4095
    int lane = tid & 31, ks = (tid >> 5) & 15, mb = tid >> 9;
    int r = lane >> 2, c0 = (lane & 3) * 2;
    int row0 = mb * 16 + r, row1 = row0 + 8;
    int col0 = ks * 16 + c0, col2 = col0 + 8;
    float e[8];
    e[0] = Wsat[row0*CIN + col0]     * 16.f;
    e[1] = Wsat[row0*CIN + col0 + 1] * 16.f;
    e[2] = Wsat[row1*CIN + col0]     * 16.f;
    e[3] = Wsat[row1*CIN + col0 + 1] * 16.f;
    e[4] = Wsat[row0*CIN + col2]     * 16.f;
    e[5] = Wsat[row0*CIN + col2 + 1] * 16.f;
    e[6] = Wsat[row1*CIN + col2]     * 16.f;
    e[7] = Wsat[row1*CIN + col2 + 1] * 16.f;
    g_WfH[tid] = make_uint4(packh2(e[0],e[1]), packh2(e[2],e[3]),
                            packh2(e[4],e[5]), packh2(e[6],e[7]));
}

// ---------------- K1: nf = score * normalize(node_features @ Wn + bn) ------
__global__ void k_nf(const float* __restrict__ nfeat,
                     const float* __restrict__ Wn,
                     const float* __restrict__ bn,
                     const float* __restrict__ scores) {
    __shared__ float sf[8][CIN];
    __shared__ float red[8][128];
    __shared__ float sinv[8];
    int t = threadIdx.x;
    int cid = blockIdx.x;
    int b = cid >> 5;
    int n0 = (cid & 31) * 8;
    const float* src = nfeat + ((size_t)(b * Nv + n0)) * CIN;
    #pragma unroll
    for (int r = 0; r < 16; r++) {
        int idx = r * 128 + t;
        sf[idx >> 8][idx & 255] = src[idx];
    }
    __syncthreads();
    float acc[8];
    float bj = bn[t];
    #pragma unroll
    for (int i = 0; i < 8; i++) acc[i] = bj;
    for (int k = 0; k < CIN; k++) {
        float w = Wn[k * CH + t];
        #pragma unroll
        for (int i = 0; i < 8; i++) acc[i] += sf[i][k] * w;
    }
    #pragma unroll
    for (int i = 0; i < 8; i++) red[i][t] = acc[i] * acc[i];
    __syncthreads();
    if (t < 8) {
        float s = 0.f;
        for (int j = 0; j < 128; j++) s += red[t][j];
        sinv[t] = scores[b * Nv + n0 + t] / fmaxf(sqrtf(s), 1e-12f);
    }
    __syncthreads();
    #pragma unroll
    for (int i = 0; i < 8; i++)
        g_nf[(size_t)(b * Nv + n0 + i) * CH + t] = acc[i] * sinv[i];
}

// ---------------- K2: per-node projected ray endpoints ---------------------
__global__ void k_pw(const float* __restrict__ coords,
                     const float* __restrict__ depths,
                     const float* __restrict__ Kl,
                     const float* __restrict__ Rl,
                     const float* __restrict__ Ks,
                     const float* __restrict__ Rs) {
    int idx = blockIdx.x * blockDim.x + threadIdx.x;
    if (idx >= Bv * Nv) return;
    int b = idx / Nv;
    const float* K = Kl + b * 9;
    float a00=K[0],a01=K[1],a02=K[2],a10=K[3],a11=K[4],a12=K[5],a20=K[6],a21=K[7],a22=K[8];
    float c00 = a11*a22 - a12*a21, c01 = a02*a21 - a01*a22, c02 = a01*a12 - a02*a11;
    float c10 = a12*a20 - a10*a22, c11 = a00*a22 - a02*a20, c12 = a02*a10 - a00*a12;
    float c20 = a10*a21 - a11*a20, c21 = a01*a20 - a00*a21, c22 = a00*a11 - a01*a10;
    float det = a00*c00 + a01*c10 + a02*c20;
    float id = 1.0f / det;
    float u = coords[idx*2+0], v = coords[idx*2+1];
    float d = depths[idx];
    float cx = (c00*u + c01*v + c02) * id * d;
    float cy = (c10*u + c11*v + c12) * id * d;
    float cz = (c20*u + c21*v + c22) * id * d;
    const float* R = Rl + b * 9;
    float wx = R[0]*cx + R[1]*cy + R[2]*cz;
    float wy = R[3]*cx + R[4]*cy + R[5]*cz;
    float wz = R[6]*cx + R[7]*cy + R[8]*cz;
    const float* Km = Ks + b * 9;
    const float* Rm = Rs + b * 9;
    float P[9];
    #pragma unroll
    for (int i = 0; i < 3; i++)
        #pragma unroll
        for (int j = 0; j < 3; j++)
            P[i*3+j] = Km[i*3+0]*Rm[j*3+0] + Km[i*3+1]*Rm[j*3+1] + Km[i*3+2]*Rm[j*3+2];
    g_pw[idx*4+0] = P[0]*wx + P[1]*wy + P[2]*wz;
    g_pw[idx*4+1] = P[3]*wx + P[4]*wy + P[5]*wz;
    g_pw[idx*4+2] = P[6]*wx + P[7]*wy + P[8]*wz;
    g_pw[idx*4+3] = 0.f;
}

// ---------------- K3: sf_norm, single-fp16 A via LDG, B via cp.async -------
#define B_PITCH 272
#define BBUF    8704
#define OFF_B   0
#define OFF_S   17408
#define SMEM_K3 67584    // epilogue stage (128 x 132 fp32) dominates

__global__ __launch_bounds__(256, 2) void k_sfmma(const float* __restrict__ feat,
                                                  const float* __restrict__ bsat) {
    extern __shared__ char dsm[];
    __shared__ float s_inv[128];
    uint32_t sb = s2u(dsm);

    int t = threadIdx.x, wid = t >> 5, lane = t & 31;
    int warp_m = wid & 3, warp_n = wid >> 2;
    int b = blockIdx.y, p0 = blockIdx.x * 128;
    const float* fb = feat + (size_t)b * CIN * HW + p0;

    auto issueB = [&](int chunk){
        #pragma unroll
        for (int j = 0; j < 4; j++) {
            int idx = j * 256 + t;
            int c = idx >> 5, pxg = idx & 31;
            cpa16(sb + OFF_S + idx * 16, fb + (size_t)(chunk * 32 + c) * HW + pxg * 4);
        }
        cpa_commit();
    };
    auto convB = [&](int buf){
        #pragma unroll
        for (int j = 0; j < 4; j++) {
            int idx = j * 256 + t;
            int c = idx >> 5, pxg = idx & 31;
            float4 v = *(const float4*)(dsm + OFF_S + idx * 16);
            uint2 u = make_uint2(packh2(v.x, v.y), packh2(v.z, v.w));
            *(uint2*)(dsm + OFF_B + buf * BBUF + c * B_PITCH + pxg * 8) = u;
        }
    };

    issueB(0);
    cpa_wait0();
    convB(0);
    __syncthreads();

    uint32_t lrow = lane & 15;
    uint32_t bCol = (uint32_t)(warp_n * 64 + ((lane >> 4) & 1) * 8) * 2;
    int mb0 = warp_m * 2, mb1 = mb0 + 1;

    float acc[2][8][4];
    #pragma unroll
    for (int i = 0; i < 2; i++)
        #pragma unroll
        for (int j = 0; j < 8; j++)
            #pragma unroll
            for (int r = 0; r < 4; r++) acc[i][j][r] = 0.f;

    // A-fragment registers (current set for ksg=0)
    uint4 AH0 = __ldg(&g_WfH[(mb0 * 16 + 0) * 32 + lane]);
    uint4 AH1 = __ldg(&g_WfH[(mb1 * 16 + 0) * 32 + lane]);

    for (int c = 0; c < 8; c++) {
        if (c < 7) issueB(c + 1);
        uint32_t bbase = sb + OFF_B + (uint32_t)(c & 1) * BBUF;
        #pragma unroll
        for (int ks = 0; ks < 2; ks++) {
            int ksg = c * 2 + ks;
            int pk = (ksg < 15) ? (ksg + 1) : 15;
            uint4 nAH0 = __ldg(&g_WfH[(mb0 * 16 + pk) * 32 + lane]);
            uint4 nAH1 = __ldg(&g_WfH[(mb1 * 16 + pk) * 32 + lane]);
            uint32_t bb[4][4];
            #pragma unroll
            for (int nf2 = 0; nf2 < 4; nf2++)
                ldsm4t(bb[nf2], bbase + (uint32_t)(ks * 16 + lrow) * B_PITCH
                                      + bCol + (uint32_t)nf2 * 32);
            const uint32_t* ah[2] = {(const uint32_t*)&AH0, (const uint32_t*)&AH1};
            #pragma unroll
            for (int nf2 = 0; nf2 < 4; nf2++)
                #pragma unroll
                for (int fm = 0; fm < 2; fm++) {
                    mma16816(acc[fm][2*nf2],     ah[fm], bb[nf2] + 0);
                    mma16816(acc[fm][2*nf2 + 1], ah[fm], bb[nf2] + 2);
                }
            AH0 = nAH0; AH1 = nAH1;
        }
        if (c < 7) { cpa_wait0(); convB((c + 1) & 1); }
        __syncthreads();
    }

    // ---- epilogue: stage [px][o] (scale+bias), per-px L2 norm, fp16 store --
    float* stg = (float*)dsm;          // 128 px x 132 floats
    const float SC = 0.0625f;
    float bias0[2], bias1[2];
    #pragma unroll
    for (int fm = 0; fm < 2; fm++) {
        int m = warp_m * 32 + fm * 16 + (lane >> 2);
        bias0[fm] = bsat[m];
        bias1[fm] = bsat[m + 8];
    }
    #pragma unroll
    for (int fm = 0; fm < 2; fm++) {
        int m0 = warp_m * 32 + fm * 16 + (lane >> 2);
        #pragma unroll
        for (int fn = 0; fn < 8; fn++) {
            int n0 = warp_n * 64 + fn * 8 + (lane & 3) * 2;
            stg[n0 * 132 + m0]           = acc[fm][fn][0] * SC + bias0[fm];
            stg[(n0 + 1) * 132 + m0]     = acc[fm][fn][1] * SC + bias0[fm];
            stg[n0 * 132 + m0 + 8]       = acc[fm][fn][2] * SC + bias1[fm];
            stg[(n0 + 1) * 132 + m0 + 8] = acc[fm][fn][3] * SC + bias1[fm];
        }
    }
    __syncthreads();
    if (t < 128) {
        float ss = 0.f;
        #pragma unroll
        for (int o4 = 0; o4 < 32; o4++) {
            float4 v = *(const float4*)&stg[t * 132 + o4 * 4];
            ss += v.x*v.x + v.y*v.y + v.z*v.z + v.w*v.w;
        }
        s_inv[t] = 1.0f / fmaxf(sqrtf(ss), 1e-12f);
    }
    __syncthreads();
    __half* outp = g_sfnh + ((size_t)b * HW + p0) * CH;
    #pragma unroll
    for (int it = 0; it < 8; it++) {
        int idx = it * 256 + t;
        int px = idx >> 4, cg = (idx & 15) * 8;
        float inv = s_inv[px];
        float4 v0 = *(const float4*)&stg[px * 132 + cg];
        float4 v1 = *(const float4*)&stg[px * 132 + cg + 4];
        uint4 o;
        o.x = packh2(v0.x * inv, v0.y * inv);
        o.y = packh2(v0.z * inv, v0.w * inv);
        o.z = packh2(v1.x * inv, v1.y * inv);
        o.w = packh2(v1.z * inv, v1.w * inv);
        *(uint4*)(outp + (size_t)px * CH + cg) = o;
    }
}

// ---------------- K4: 2 search positions per block -------------------------
__global__ __launch_bounds__(256) void k_sample(const float* __restrict__ Ksat,
                                                const float* __restrict__ Rsat,
                                                const float* __restrict__ tsat,
                                                const float* __restrict__ tinit,
                                                const float* __restrict__ radius) {
    int b = blockIdx.y;
    int s0 = blockIdx.x * 2;
    int t = threadIdx.x;
    int w = t >> 5, lane = t & 31;
    __shared__ float warpsum[2][8];
    float rxs[2], rys[2], rzs[2];
    {
        const float* Km = Ksat + b * 9;
        const float* Rm = Rsat + b * 9;
        float rad = radius[b];
        float stepx = -1.f + (float)(s0 & 15) * (2.f / 15.f);
        float stepy = -1.f + (float)(s0 >> 4) * (2.f / 15.f);
        float dx = tinit[b*3+0] + stepx * rad - tsat[b*3+0];
        float dy = tinit[b*3+1] + stepy * rad - tsat[b*3+1];
        float dz = tinit[b*3+2] - tsat[b*3+2];
        float P[9];
        #pragma unroll
        for (int i = 0; i < 3; i++)
            #pragma unroll
            for (int j = 0; j < 3; j++)
                P[i*3+j] = Km[i*3+0]*Rm[j*3+0] + Km[i*3+1]*Rm[j*3+1] + Km[i*3+2]*Rm[j*3+2];
        rxs[0] = P[0]*dx + P[1]*dy + P[2]*dz;
        rys[0] = P[3]*dx + P[4]*dy + P[5]*dz;
        rzs[0] = P[6]*dx + P[7]*dy + P[8]*dz;
        float ddx = (2.f / 15.f) * rad;
        rxs[1] = rxs[0] + P[0] * ddx;
        rys[1] = rys[0] + P[3] * ddx;
        rzs[1] = rzs[0] + P[6] * ddx;
    }

    const float PXS = 256.0f / 255.0f;
    const __half* sfb = g_sfnh + (size_t)b * HW * CH;
    float lacc[2] = {0.f, 0.f};
    #pragma unroll 1
    for (int n = w; n < Nv; n += 8) {
        float4 pw  = *(const float4*)(g_pw + (b * Nv + n) * 4);
        float4 nfv = *(const float4*)(g_nf + (size_t)(b * Nv + n) * CH + lane * 4);
        #pragma unroll
        for (int sc = 0; sc < 2; sc++) {
            float ww = pw.z + rzs[sc];
            float cx = (pw.x + rxs[sc]) / ww;
            float cy = (pw.y + rys[sc]) / ww;
            if (lane == 0) {
                float2* cd = (float2*)(g_cand + ((size_t)(b*Sv + s0 + sc) * Nv) * 2);
                cd[n] = make_float2(cx, cy);
            }
            float px = cx * PXS - 0.5f, py = cy * PXS - 0.5f;
            float x0 = floorf(px), y0 = floorf(py);
            float fx = px - x0, fy = py - y0;
            float cw[4] = {(1.f-fy)*(1.f-fx), (1.f-fy)*fx, fy*(1.f-fx), fy*fx};
            float acc = 0.f;
            #pragma unroll
            for (int cc = 0; cc < 4; cc++) {
                float xf = x0 + (float)(cc & 1), yf = y0 + (float)(cc >> 1);
                float m = (xf >= 0.f && xf <= 255.f && yf >= 0.f && yf <= 255.f) ? 1.f : 0.f;
                int xi = min(max((int)xf, 0), 255), yi = min(max((int)yf, 0), 255);
                uint2 rr = *(const uint2*)(sfb + ((size_t)(yi * Wv + xi)) * CH + lane * 4);
                float2 h0 = __half22float2(*(__half2*)&rr.x);
                float2 h1 = __half22float2(*(__half2*)&rr.y);
                float d = nfv.x*h0.x + nfv.y*h0.y + nfv.z*h1.x + nfv.w*h1.y;
                acc += cw[cc] * m * d;
            }
            lacc[sc] += acc;
        }
    }
    #pragma unroll
    for (int sc = 0; sc < 2; sc++) {
        float v = lacc[sc];
        #pragma unroll
        for (int o = 16; o > 0; o >>= 1) v += __shfl_down_sync(0xffffffffu, v, o);
        if (lane == 0) warpsum[sc][w] = v;
    }
    __syncthreads();
    if (t < 2) {
        float s8 = 0.f;
        #pragma unroll
        for (int i = 0; i < 8; i++) s8 += warpsum[t][i];
        g_logits[b * Sv + s0 + t] = s8;
    }
}

// ---------------- K5: softmax, argmax, outputs -----------------------------
__global__ void k_final(float* __restrict__ out,
                        const float* __restrict__ tinit,
                        const float* __restrict__ radius,
                        const float* __restrict__ lscale) {
    int b = blockIdx.x;
    int t = threadIdx.x;   // 256
    __shared__ float sred[256];
    __shared__ int bestI;
    float escale = expf(lscale[0]);
    float L = g_logits[b * Sv + t] * escale;
    sred[t] = L; __syncthreads();
    for (int o = 128; o > 0; o >>= 1) {
        if (t < o) sred[t] = fmaxf(sred[t], sred[t + o]);
        __syncthreads();
    }
    float m = sred[0];
    __syncthreads();
    float e = expf(L - m);
    sred[t] = e; __syncthreads();
    for (int o = 128; o > 0; o >>= 1) {
        if (t < o) sred[t] += sred[t + o];
        __syncthreads();
    }
    float Z = sred[0];
    out[6144 + b * Sv + t] = e / Z;
    if (t == 0) bestI = 1 << 30;
    __syncthreads();
    if (L == m) atomicMin(&bestI, t);
    __syncthreads();
    int bi = bestI;
    float mx = g_cand[((size_t)(b * Sv + bi) * Nv + t) * 2 + 0];
    float my = g_cand[((size_t)(b * Sv + bi) * Nv + t) * 2 + 1];
    out[(b * Nv + t) * 2 + 0] = mx;
    out[(b * Nv + t) * 2 + 1] = my;
    out[2048 + b * Nv + t] =
        (mx >= 0.f && mx < (float)Wv && my >= 0.f && my < (float)Hv) ? 1.f : 0.f;
    float rad = radius[b];
    float sx = -1.f + (float)(t & 15) * (2.f / 15.f);
    float sy = -1.f + (float)(t >> 4) * (2.f / 15.f);
    out[3072 + (b * Sv + t) * 3 + 0] = tinit[b*3+0] + sx * rad;
    out[3072 + (b * Sv + t) * 3 + 1] = tinit[b*3+1] + sy * rad;
    out[3072 + (b * Sv + t) * 3 + 2] = tinit[b*3+2];
}

// ---------------- launch ----------------------------------------------------
extern "C" void kernel_launch(void* const* d_in, const int* in_sizes, int n_in,
                              void* d_out, int out_size) {
    const float* node_coords   = (const float*)d_in[0];
    const float* node_scores   = (const float*)d_in[1];
    const float* node_features = (const float*)d_in[2];
    const float* node_depths   = (const float*)d_in[3];
    const float* K_left        = (const float*)d_in[4];
    const float* R_left        = (const float*)d_in[5];
    const float* t_init        = (const float*)d_in[6];
    const float* sat_featmap   = (const float*)d_in[7];
    const float* K_sat         = (const float*)d_in[8];
    const float* R_sat         = (const float*)d_in[9];
    const float* t_sat         = (const float*)d_in[10];
    const float* radius        = (const float*)d_in[11];
    int off = (n_in >= 18) ? 0 : -1;
    const float* W_node      = (const float*)d_in[13 + off];
    const float* b_node      = (const float*)d_in[14 + off];
    const float* W_sat       = (const float*)d_in[15 + off];
    const float* b_sat       = (const float*)d_in[16 + off];
    const float* logit_scale = (const float*)d_in[17 + off];
    float* out = (float*)d_out;

    cudaFuncSetAttribute(k_sfmma, cudaFuncAttributeMaxDynamicSharedMemorySize, SMEM_K3);

    k_wcvt<<<16, 256>>>(W_sat);
    k_nf<<<128, 128>>>(node_features, W_node, b_node, node_scores);
    k_pw<<<4, 256>>>(node_coords, node_depths, K_left, R_left, K_sat, R_sat);
    k_sfmma<<<dim3(512, Bv), 256, SMEM_K3>>>(sat_featmap, b_sat);
    k_sample<<<dim3(Sv/2, Bv), 256>>>(K_sat, R_sat, t_sat, t_init, radius);
    k_final<<<Bv, 256>>>(out, t_init, radius, logit_scale);
}